// round 15
// baseline (speedup 1.0000x reference)
#include <cuda_runtime.h>
#include <cuda_bf16.h>
#include <cuda_fp16.h>
#include <cstdint>
#include <math.h>

// Problem constants
#define BSZ 4
#define SEQ 1024
#define DMODEL 1024
#define NHEAD 16
#define DHEAD 64
#define LPE 2045   // 2*s-1, s = 1023

// Scratch (all operands fp16)
__device__ __half g_xh  [BSZ * SEQ * DMODEL];
__device__ __half g_wqkvh[DMODEL * 3 * DMODEL];
__device__ __half g_wpeh [DMODEL * DMODEL];
__device__ __half g_woh  [DMODEL * DMODEL];
__device__ __half g_qkvh[BSZ * SEQ * 3 * DMODEL];
__device__ __half g_peh [LPE * DMODEL];
__device__ __half g_pekh[LPE * DMODEL];
__device__ __half g_aoh [BSZ * SEQ * DMODEL];
__device__ float  g_pbias[NHEAD * 2048];

// ---------------------------------------------------------------------------
__device__ __forceinline__ void mma_f16(float* d, const uint32_t* a,
                                        const uint32_t* b) {
    asm volatile(
        "mma.sync.aligned.m16n8k16.row.col.f32.f16.f16.f32 "
        "{%0,%1,%2,%3}, {%4,%5,%6,%7}, {%8,%9}, {%0,%1,%2,%3};\n"
        : "+f"(d[0]), "+f"(d[1]), "+f"(d[2]), "+f"(d[3])
        : "r"(a[0]), "r"(a[1]), "r"(a[2]), "r"(a[3]),
          "r"(b[0]), "r"(b[1]));
}

__device__ __forceinline__ uint32_t pack_h2(float x, float y) {
    __half2 h = __floats2half2_rn(x, y);
    return *(uint32_t*)&h;
}

__device__ __forceinline__ uint32_t cvta_smem(const void* p) {
    uint32_t a;
    asm("{ .reg .u64 t; cvta.to.shared.u64 t, %1; cvt.u32.u64 %0, t; }"
        : "=r"(a) : "l"(p));
    return a;
}

__device__ __forceinline__ void ldsm_x4(uint32_t* r, uint32_t a) {
    asm volatile("ldmatrix.sync.aligned.m8n8.x4.shared.b16 {%0,%1,%2,%3}, [%4];"
                 : "=r"(r[0]), "=r"(r[1]), "=r"(r[2]), "=r"(r[3]) : "r"(a));
}
__device__ __forceinline__ void ldsm_x4_t(uint32_t* r, uint32_t a) {
    asm volatile("ldmatrix.sync.aligned.m8n8.x4.trans.shared.b16 {%0,%1,%2,%3}, [%4];"
                 : "=r"(r[0]), "=r"(r[1]), "=r"(r[2]), "=r"(r[3]) : "r"(a));
}
__device__ __forceinline__ void ldsm_x2(uint32_t* r, uint32_t a) {
    asm volatile("ldmatrix.sync.aligned.m8n8.x2.shared.b16 {%0,%1}, [%2];"
                 : "=r"(r[0]), "=r"(r[1]) : "r"(a));
}

__device__ __forceinline__ void cp16(uint32_t dst, const void* src, int nbytes) {
    asm volatile("cp.async.cg.shared.global [%0], [%1], 16, %2;"
                 :: "r"(dst), "l"(src), "r"(nbytes));
}
#define CP_COMMIT asm volatile("cp.async.commit_group;")
#define CP_WAIT0  asm volatile("cp.async.wait_group 0;")
#define CP_WAIT1  asm volatile("cp.async.wait_group 1;")

// XOR-swizzled row layouts
__device__ __forceinline__ int swz32(int row, int cp) {       // 32-u32 rows
    return row * 32 + ((((cp >> 2) ^ (row & 7)) << 2) | (cp & 3));
}
__device__ __forceinline__ int swz64(int row, int cp) {       // 64-u32 rows
    return row * 64 + ((((cp >> 2) ^ (row & 7)) << 2) | (cp & 3));
}

// ---------------------------------------------------------------------------
__global__ void f2h_kernel(const float* __restrict__ in, __half* __restrict__ out,
                           int n) {
    int i = (blockIdx.x * blockDim.x + threadIdx.x) * 4;
    if (i >= n) return;
    float4 v = *(const float4*)(in + i);
    uint2 o;
    o.x = pack_h2(v.x, v.y);
    o.y = pack_h2(v.z, v.w);
    *(uint2*)(out + i) = o;
}

__global__ void pegen_kernel(__half* __restrict__ peh) {
    int idx = blockIdx.x * blockDim.x + threadIdx.x;
    if (idx >= LPE * DMODEL) return;
    int l  = idx >> 10;
    int kk = idx & 1023;
    int p2 = kk & ~1;
    float expnt = (float)p2 / 1024.0f;
    float denom = powf(10000.0f, expnt);
    float t = (float)(l - 1022);
    float ang = t / denom;
    float v = (kk & 1) ? cosf(ang) : sinf(ang);
    peh[idx] = __float2half_rn(v * 0.03125f);
}

// pbias[h][l]; warp per (h,l)
__global__ void pbias_kernel(const __half* __restrict__ pek,
                             const float* __restrict__ cb,
                             const float* __restrict__ pb,
                             float* __restrict__ pbias) {
    int gw = (blockIdx.x * blockDim.x + threadIdx.x) >> 5;
    int lane = threadIdx.x & 31;
    if (gw >= NHEAD * 2048) return;
    int h = gw >> 11, l = gw & 2047;
    float s = 0.0f;
    if (l < LPE) {
        const __half* row = pek + (size_t)l * DMODEL + h * DHEAD;
        float d0 = pb[h * DHEAD + lane]      - cb[h * DHEAD + lane];
        float d1 = pb[h * DHEAD + 32 + lane] - cb[h * DHEAD + 32 + lane];
        s = d0 * __half2float(row[lane]) + d1 * __half2float(row[32 + lane]);
#pragma unroll
        for (int off = 16; off; off >>= 1)
            s += __shfl_xor_sync(0xffffffffu, s, off);
    }
    if (lane == 0) pbias[gw] = s;
}

// ===========================================================================
// All-half GEMM: 3-stage cp.async pipeline + ldmatrix fragments.
// C[M,N] = A[M,K] @ B[K,N].  BM=128, BN=128, BK=64, 256 threads.
// Stage layout: s*8192 u32 { A: 4096 u32 (128r x 32u32 swz32),
//                            B: 4096 u32 (64k x 64u32 swz64) }.
// ===========================================================================
#define STG_U32 8192
#define GEMMH_SMEM_BYTES (3 * STG_U32 * 4)   // 96 KB

template <bool C_HALF>
__global__ __launch_bounds__(256)
void gemm_h_kernel(const __half* __restrict__ A, const __half* __restrict__ B,
                   void* __restrict__ Cv, int M, int N, int K) {
    extern __shared__ uint32_t smu[];
    uint32_t smemb = cvta_smem(smu);

    float*  Cf = (float*)Cv;
    __half* Ch = (__half*)Cv;

    int tid  = threadIdx.x;
    int wid  = tid >> 5;
    int lane = tid & 31;
    int g    = lane >> 2;
    int tg   = lane & 3;
    int wm0  = (wid >> 2) * 64;
    int wn0  = (wid & 3) * 32;
    int bm = blockIdx.y * 128;
    int bn = blockIdx.x * 128;

    int rA = (lane & 7) + 8 * ((lane >> 3) & 1);
    int cA = 4 * (lane >> 4);
    int rV = lane & 15;
    int cV = 4 * (lane >> 4);

    float acc[4][4][4];
#pragma unroll
    for (int mt = 0; mt < 4; mt++)
#pragma unroll
        for (int nt = 0; nt < 4; nt++)
#pragma unroll
            for (int r = 0; r < 4; r++) acc[mt][nt][r] = 0.0f;

    auto stage = [&](int s, int k0) {
        uint32_t asB = smemb + (s * STG_U32) * 4;
        uint32_t bsB = asB + 4096 * 4;
#pragma unroll
        for (int it = 0; it < 4; it++) {
            int idx = tid + 256 * it;
            int i = idx >> 3, gq = idx & 7;
            int gr = bm + i;
            uint32_t dst = asB + 4 * (i * 32 + ((gq ^ (i & 7)) << 2));
            cp16(dst, A + (size_t)gr * K + k0 + 8 * gq, gr < M ? 16 : 0);
        }
#pragma unroll
        for (int it = 0; it < 4; it++) {
            int idx = tid + 256 * it;
            int kr = idx >> 4, cq = idx & 15;
            uint32_t dst = bsB + 4 * (kr * 64 + ((cq ^ (kr & 7)) << 2));
            cp16(dst, B + (size_t)(k0 + kr) * N + bn + 8 * cq, 16);
        }
    };

    auto compute = [&](int s) {
        uint32_t asB = smemb + (s * STG_U32) * 4;
        uint32_t bsB = asB + 4096 * 4;
#pragma unroll
        for (int kc = 0; kc < 4; kc++) {
            uint32_t af[4][4], bf[2][4];
#pragma unroll
            for (int mt = 0; mt < 4; mt++)
                ldsm_x4(af[mt], asB + 4 * swz32(wm0 + 16 * mt + rA, 8 * kc + cA));
#pragma unroll
            for (int np = 0; np < 2; np++)
                ldsm_x4_t(bf[np], bsB + 4 * swz64(16 * kc + rV,
                                                  wn0 / 2 + 8 * np + cV));
#pragma unroll
            for (int mt = 0; mt < 4; mt++)
#pragma unroll
                for (int np = 0; np < 2; np++) {
                    mma_f16(acc[mt][2 * np],     af[mt], bf[np]);
                    mma_f16(acc[mt][2 * np + 1], af[mt], bf[np] + 2);
                }
        }
    };

    int T = K >> 6;
    stage(0, 0);
    CP_COMMIT;
    if (T > 1) { stage(1, 64); CP_COMMIT; }

    int sidx = 0;
    for (int t = 0; t < T; t++) {
        if (t + 1 < T) { CP_WAIT1; } else { CP_WAIT0; }
        __syncthreads();
        if (t + 2 < T) {
            int sn = sidx + 2; if (sn >= 3) sn -= 3;
            stage(sn, (t + 2) << 6);
            CP_COMMIT;
        }
        compute(sidx);
        __syncthreads();      // reads done before this buffer is re-staged
        if (++sidx == 3) sidx = 0;
    }

#pragma unroll
    for (int mt = 0; mt < 4; mt++) {
        int r0 = bm + wm0 + mt * 16 + g;
        int r1 = r0 + 8;
#pragma unroll
        for (int nt = 0; nt < 4; nt++) {
            int col = bn + wn0 + nt * 8 + 2 * tg;
            if (C_HALF) {
                if (r0 < M)
                    *(uint32_t*)(Ch + (size_t)r0 * N + col) =
                        pack_h2(acc[mt][nt][0], acc[mt][nt][1]);
                if (r1 < M)
                    *(uint32_t*)(Ch + (size_t)r1 * N + col) =
                        pack_h2(acc[mt][nt][2], acc[mt][nt][3]);
            } else {
                if (r0 < M)
                    *(float2*)(Cf + (size_t)r0 * N + col) =
                        make_float2(acc[mt][nt][0], acc[mt][nt][1]);
                if (r1 < M)
                    *(float2*)(Cf + (size_t)r1 * N + col) =
                        make_float2(acc[mt][nt][2], acc[mt][nt][3]);
            }
        }
    }
}

// ===========================================================================
// Attention v8 (unchanged from R14): double-buffered cp.async K/V staging,
// ldmatrix fragments, PE ring, pos-bias folded.  512 threads, 1 CTA/SM.
// ===========================================================================
#define A8_KS 0
#define A8_VS 4096
#define A8_PE 8192
#define A8_BIAS 20480
#define A8_MSK 20864
#define A8_U 20928
#define A8_SMEM_BYTES (42432 * 4)
#define SPAD 84
#define SLAB5 1344

__global__ __launch_bounds__(512, 1)
void attn_mma8_kernel(const __half* __restrict__ qkvh,
                      const __half* __restrict__ pekh,
                      const unsigned char* __restrict__ mask,
                      const float* __restrict__ cb,
                      const float* __restrict__ pbias,
                      __half* __restrict__ aoh) {
    extern __shared__ float sm[];
    uint32_t* PElu = (uint32_t*)sm + A8_PE;
    float* Bias = sm + A8_BIAS;
    float* Msk  = sm + A8_MSK;
    float* U    = sm + A8_U;
    uint32_t* Qs = (uint32_t*)U;
    uint32_t smemb = cvta_smem(sm);

    int tid = threadIdx.x;
    int w = tid >> 5;
    int lane = tid & 31;
    int g = lane >> 2;
    int tg = lane & 3;
    int qt = blockIdx.x & 3;
    int bh = blockIdx.x >> 2;
    int h  = bh & 15;
    int b  = bh >> 4;
    int q0 = qt * 256;

    uint32_t ksB = smemb + A8_KS * 4;
    uint32_t vsB = smemb + A8_VS * 4;
    uint32_t peB = smemb + A8_PE * 4;
    uint32_t pB  = smemb + (A8_U + w * SLAB5) * 4;

    int rA = (lane & 7) + 8 * ((lane >> 3) & 1);
    int cA = 4 * (lane >> 4);
    int rB = 8 * (lane >> 4) + (lane & 7);
    int cB = 4 * ((lane >> 3) & 1);
    int rV = lane & 15;
    int cV = 4 * (lane >> 4);

    const float* cbh = cb + h * DHEAD;
    const float* pbh_bias = pbias + h * 2048;
    int lbase0 = 767 - q0;

    auto stage_kv = [&](int s, int k0s) {
        int i = tid >> 3, gq = tid & 7;
        size_t base = ((size_t)(b * SEQ + k0s + i)) * 3072 + h * 192;
        uint32_t off = 4 * (i * 32 + ((gq ^ (i & 7)) << 2));
        cp16(ksB + s * 8192 + off, qkvh + base + 64 + 8 * gq, 16);
        cp16(vsB + s * 8192 + off, qkvh + base + 128 + 8 * gq, 16);
    };

    stage_kv(0, 0);
    CP_COMMIT;

    // ---- Prologue: Qc, PE [0,320), Bias ----
    for (int idx = tid; idx < 2048; idx += 512) {
        int i = idx >> 3, gq = idx & 7;
        int c8 = gq * 8;
        uint4 v = *(const uint4*)(qkvh + ((size_t)(b * SEQ + q0 + i)) * 3072
                                  + h * 192 + c8);
        __half2* hp = (__half2*)&v;
        uint4 o;
#pragma unroll
        for (int e = 0; e < 4; e++) {
            float2 f = __half22float2(hp[e]);
            ((uint32_t*)&o)[e] = pack_h2(f.x + cbh[c8 + 2 * e],
                                         f.y + cbh[c8 + 2 * e + 1]);
        }
        *(uint4*)(Qs + i * 32 + ((gq ^ (i & 7)) << 2)) = o;
    }
    for (int idx = tid; idx < 2560; idx += 512) {
        int sl_ = idx >> 3, gq = idx & 7;
        int lg = lbase0 + sl_;
        uint4 v = (lg >= 0 && lg < LPE)
            ? *(const uint4*)(pekh + (size_t)lg * DMODEL + h * DHEAD + 8 * gq)
            : make_uint4(0u, 0u, 0u, 0u);
        *(uint4*)(PElu + sl_ * 32 + ((gq ^ (sl_ & 7)) << 2)) = v;
    }
    if (tid < 320) {
        int lg = lbase0 + tid;
        Bias[tid] = (lg >= 0 && lg < LPE) ? pbh_bias[lg] : 0.0f;
    }
    __syncthreads();

    uint32_t qcf[4][4];
    int r0l = 16 * w + g, r1l = r0l + 8;
#pragma unroll
    for (int kc = 0; kc < 4; kc++) {
        qcf[kc][0] = Qs[swz32(r0l, 8 * kc + tg)];
        qcf[kc][1] = Qs[swz32(r1l, 8 * kc + tg)];
        qcf[kc][2] = Qs[swz32(r0l, 8 * kc + tg + 4)];
        qcf[kc][3] = Qs[swz32(r1l, 8 * kc + tg + 4)];
    }

    bool zq0 = (q0 == 0 && w == 0 && g == 0);

    float oac[8][4];
#pragma unroll
    for (int nt = 0; nt < 8; nt++)
#pragma unroll
        for (int r = 0; r < 4; r++) oac[nt][r] = 0.0f;
    float m0 = -1e30f, m1 = -1e30f, l0 = 0.0f, l1 = 0.0f;

    float* slab = U + w * SLAB5;
    uint32_t* P32 = (uint32_t*)slab;
    int s0base = 30 - 2 * w;

    for (int kt = 0; kt < 16; kt++) {
        int k0 = kt * 64;
        int ktm = (64 * kt) % 384;
        int s = kt & 1;
        __syncthreads();

        if (kt < 15) {
            stage_kv(s ^ 1, k0 + 64);
            CP_COMMIT;
            {
                int r = tid >> 3, gq = tid & 7;
                int off = 64 * kt + 320 + r;
                int slot = off % 384;
                int lg = lbase0 + off;
                uint4 v = (lg >= 0 && lg < LPE)
                    ? *(const uint4*)(pekh + (size_t)lg * DMODEL + h * DHEAD + 8 * gq)
                    : make_uint4(0u, 0u, 0u, 0u);
                *(uint4*)(PElu + slot * 32 + ((gq ^ (slot & 7)) << 2)) = v;
            }
            if (tid < 64) {
                int off = 64 * kt + 320 + tid;
                int lg = lbase0 + off;
                Bias[off % 384] = (lg >= 0 && lg < LPE) ? pbh_bias[lg] : 0.0f;
            }
        }
        if (tid < 64) Msk[tid] = mask[b * SEQ + k0 + tid] ? -1e30f : 0.0f;

        if (kt < 15) { CP_WAIT1; } else { CP_WAIT0; }
        __syncthreads();

        uint32_t ksS = ksB + s * 8192;
        uint32_t vsS = vsB + s * 8192;

#pragma unroll
        for (int t = 0; t < 10; t++) {
            int m = s0base + t;
            int sr = ktm + 8 * m; if (sr >= 384) sr -= 384;
            float sp[4] = {0.f, 0.f, 0.f, 0.f};
            int rowP = sr + (lane & 7);
#pragma unroll
            for (int kc = 0; kc < 4; kc++) {
                uint32_t bf[2];
                ldsm_x2(bf, peB + 4 * swz32(rowP, 8 * kc + cB));
                mma_f16(sp, qcf[kc], bf);
            }
            int bidx = ktm + 8 * m + 2 * tg; if (bidx >= 384) bidx -= 384;
            float b0 = Bias[bidx], b1 = Bias[bidx + 1];
            int cc0 = 8 * t + 2 * tg;
            slab[g * SPAD + cc0]           = sp[0] + b0;
            slab[g * SPAD + cc0 + 1]       = sp[1] + b1;
            slab[(g + 8) * SPAD + cc0]     = sp[2] + b0;
            slab[(g + 8) * SPAD + cc0 + 1] = sp[3] + b1;
        }
        __syncwarp();

        float sc[8][4];
#pragma unroll
        for (int nt = 0; nt < 8; nt++)
#pragma unroll
            for (int r = 0; r < 4; r++) sc[nt][r] = 0.0f;
#pragma unroll
        for (int ntp = 0; ntp < 4; ntp++) {
            int rowK = 16 * ntp + rB;
#pragma unroll
            for (int kc = 0; kc < 4; kc++) {
                uint32_t r[4];
                ldsm_x4(r, ksS + 4 * swz32(rowK, 8 * kc + cB));
                mma_f16(sc[2 * ntp],     qcf[kc], r);
                mma_f16(sc[2 * ntp + 1], qcf[kc], r + 2);
            }
        }

        float mt0 = -1e30f, mt1 = -1e30f;
#pragma unroll
        for (int nt = 0; nt < 8; nt++) {
            int j0 = nt * 8 + 2 * tg;
            int c00 = j0 - g + 15;
            int c10 = j0 - g + 7;
            float p0 = slab[g * SPAD + c00];
            float p1 = slab[g * SPAD + c00 + 1];
            float p2 = slab[(g + 8) * SPAD + c10];
            float p3 = slab[(g + 8) * SPAD + c10 + 1];
            if (kt == 0 && nt == 0 && tg == 0) { p0 = 0.0f; p2 = 0.0f; }
            if (zq0) { p0 = 0.0f; p1 = 0.0f; }
            float mk0 = Msk[j0], mk1 = Msk[j0 + 1];
            sc[nt][0] = (sc[nt][0] + p0) * 0.125f + mk0;
            sc[nt][1] = (sc[nt][1] + p1) * 0.125f + mk1;
            sc[nt][2] = (sc[nt][2] + p2) * 0.125f + mk0;
            sc[nt][3] = (sc[nt][3] + p3) * 0.125f + mk1;
            mt0 = fmaxf(mt0, fmaxf(sc[nt][0], sc[nt][1]));
            mt1 = fmaxf(mt1, fmaxf(sc[nt][2], sc[nt][3]));
        }
        mt0 = fmaxf(mt0, __shfl_xor_sync(0xffffffffu, mt0, 1));
        mt0 = fmaxf(mt0, __shfl_xor_sync(0xffffffffu, mt0, 2));
        mt1 = fmaxf(mt1, __shfl_xor_sync(0xffffffffu, mt1, 1));
        mt1 = fmaxf(mt1, __shfl_xor_sync(0xffffffffu, mt1, 2));

        float mn0 = fmaxf(m0, mt0), mn1 = fmaxf(m1, mt1);
        float c0 = __expf(m0 - mn0), c1 = __expf(m1 - mn1);
        m0 = mn0; m1 = mn1;
#pragma unroll
        for (int nt = 0; nt < 8; nt++) {
            oac[nt][0] *= c0; oac[nt][1] *= c0;
            oac[nt][2] *= c1; oac[nt][3] *= c1;
        }
        float rs0 = 0.0f, rs1 = 0.0f;
#pragma unroll
        for (int nt = 0; nt < 8; nt++) {
            sc[nt][0] = __expf(sc[nt][0] - mn0);
            sc[nt][1] = __expf(sc[nt][1] - mn0);
            sc[nt][2] = __expf(sc[nt][2] - mn1);
            sc[nt][3] = __expf(sc[nt][3] - mn1);
            rs0 += sc[nt][0] + sc[nt][1];
            rs1 += sc[nt][2] + sc[nt][3];
        }
        rs0 += __shfl_xor_sync(0xffffffffu, rs0, 1);
        rs0 += __shfl_xor_sync(0xffffffffu, rs0, 2);
        rs1 += __shfl_xor_sync(0xffffffffu, rs1, 1);
        rs1 += __shfl_xor_sync(0xffffffffu, rs1, 2);
        l0 = l0 * c0 + rs0;
        l1 = l1 * c1 + rs1;

        __syncwarp();

#pragma unroll
        for (int nt = 0; nt < 8; nt++) {
            P32[swz32(g,     4 * nt + tg)] = pack_h2(sc[nt][0], sc[nt][1]);
            P32[swz32(g + 8, 4 * nt + tg)] = pack_h2(sc[nt][2], sc[nt][3]);
        }
        __syncwarp();

        uint32_t pf[4][4];
#pragma unroll
        for (int kc = 0; kc < 4; kc++)
            ldsm_x4(pf[kc], pB + 4 * swz32(rA, 8 * kc + cA));
#pragma unroll
        for (int ntp = 0; ntp < 4; ntp++) {
            int cpV = 8 * ntp + cV;
#pragma unroll
            for (int kc = 0; kc < 4; kc++) {
                uint32_t r[4];
                ldsm_x4_t(r, vsS + 4 * swz32(16 * kc + rV, cpV));
                mma_f16(oac[2 * ntp],     pf[kc], r);
                mma_f16(oac[2 * ntp + 1], pf[kc], r + 2);
            }
        }
    }

    float inv0 = 1.0f / l0, inv1 = 1.0f / l1;
    int r0 = q0 + r0l, r1 = q0 + r1l;
    size_t rowA = ((size_t)(b * SEQ + r0)) * DMODEL + h * DHEAD;
    size_t rowB = ((size_t)(b * SEQ + r1)) * DMODEL + h * DHEAD;
#pragma unroll
    for (int nt = 0; nt < 8; nt++) {
        int col = nt * 8 + 2 * tg;
        *(uint32_t*)(aoh + rowA + col) =
            pack_h2(oac[nt][0] * inv0, oac[nt][1] * inv0);
        *(uint32_t*)(aoh + rowB + col) =
            pack_h2(oac[nt][2] * inv1, oac[nt][3] * inv1);
    }
}

// ---------------------------------------------------------------------------
extern "C" void kernel_launch(void* const* d_in, const int* in_sizes, int n_in,
                              void* d_out, int out_size) {
    const float* x          = (const float*)d_in[0];
    const unsigned char* mk = (const unsigned char*)d_in[1];
    const float* Wqkv       = (const float*)d_in[2];
    const float* Wpe        = (const float*)d_in[3];
    const float* Wo         = (const float*)d_in[4];
    const float* cb         = (const float*)d_in[5];
    const float* pb         = (const float*)d_in[6];
    float* out              = (float*)d_out;

    __half *xh, *wqkvh, *wpeh, *woh, *qkvh, *peh, *pekh, *aoh;
    float *pbias;
    cudaGetSymbolAddress((void**)&xh,    g_xh);
    cudaGetSymbolAddress((void**)&wqkvh, g_wqkvh);
    cudaGetSymbolAddress((void**)&wpeh,  g_wpeh);
    cudaGetSymbolAddress((void**)&woh,   g_woh);
    cudaGetSymbolAddress((void**)&qkvh,  g_qkvh);
    cudaGetSymbolAddress((void**)&peh,   g_peh);
    cudaGetSymbolAddress((void**)&pekh,  g_pekh);
    cudaGetSymbolAddress((void**)&aoh,   g_aoh);
    cudaGetSymbolAddress((void**)&pbias, g_pbias);

    cudaFuncSetAttribute(gemm_h_kernel<true>,
                         cudaFuncAttributeMaxDynamicSharedMemorySize,
                         GEMMH_SMEM_BYTES);
    cudaFuncSetAttribute(gemm_h_kernel<false>,
                         cudaFuncAttributeMaxDynamicSharedMemorySize,
                         GEMMH_SMEM_BYTES);
    cudaFuncSetAttribute(attn_mma8_kernel,
                         cudaFuncAttributeMaxDynamicSharedMemorySize,
                         A8_SMEM_BYTES);

    f2h_kernel<<<(BSZ * SEQ * DMODEL / 4 + 255) / 256, 256>>>(x, xh,
                                                              BSZ * SEQ * DMODEL);
    f2h_kernel<<<(DMODEL * 3 * DMODEL / 4 + 255) / 256, 256>>>(Wqkv, wqkvh,
                                                               DMODEL * 3 * DMODEL);
    f2h_kernel<<<(DMODEL * DMODEL / 4 + 255) / 256, 256>>>(Wpe, wpeh,
                                                           DMODEL * DMODEL);
    f2h_kernel<<<(DMODEL * DMODEL / 4 + 255) / 256, 256>>>(Wo, woh,
                                                           DMODEL * DMODEL);
    pegen_kernel<<<(LPE * DMODEL + 255) / 256, 256>>>(peh);

    {
        dim3 grid(3072 / 128, 4096 / 128);
        gemm_h_kernel<true><<<grid, 256, GEMMH_SMEM_BYTES>>>(
            xh, wqkvh, qkvh, BSZ * SEQ, 3 * DMODEL, DMODEL);
    }
    {
        dim3 grid(1024 / 128, (LPE + 127) / 128);
        gemm_h_kernel<true><<<grid, 256, GEMMH_SMEM_BYTES>>>(
            peh, wpeh, pekh, LPE, DMODEL, DMODEL);
    }

    pbias_kernel<<<(NHEAD * 2048 * 32) / 256, 256>>>(pekh, cb, pb, pbias);

    attn_mma8_kernel<<<BSZ * NHEAD * (SEQ / 256), 512, A8_SMEM_BYTES>>>(
        qkvh, pekh, mk, cb, pbias, aoh);

    {
        dim3 grid(1024 / 128, 4096 / 128);
        gemm_h_kernel<false><<<grid, 256, GEMMH_SMEM_BYTES>>>(
            aoh, woh, out, BSZ * SEQ, DMODEL, DMODEL);
    }
}

// round 16
// speedup vs baseline: 1.0265x; 1.0265x over previous
#include <cuda_runtime.h>
#include <cuda_bf16.h>
#include <cuda_fp16.h>
#include <cstdint>
#include <math.h>

// Problem constants
#define BSZ 4
#define SEQ 1024
#define DMODEL 1024
#define NHEAD 16
#define DHEAD 64
#define LPE 2045   // 2*s-1, s = 1023

// Scratch (all operands fp16)
__device__ __half g_xh  [BSZ * SEQ * DMODEL];
__device__ __half g_wqkvh[DMODEL * 3 * DMODEL];
__device__ __half g_wpeh [DMODEL * DMODEL];
__device__ __half g_woh  [DMODEL * DMODEL];
__device__ __half g_qkvh[BSZ * SEQ * 3 * DMODEL];
__device__ __half g_peh [LPE * DMODEL];
__device__ __half g_pekh[LPE * DMODEL];
__device__ __half g_aoh [BSZ * SEQ * DMODEL];
__device__ float  g_pbias[NHEAD * 2048];

// ---------------------------------------------------------------------------
__device__ __forceinline__ void mma_f16(float* d, const uint32_t* a,
                                        const uint32_t* b) {
    asm volatile(
        "mma.sync.aligned.m16n8k16.row.col.f32.f16.f16.f32 "
        "{%0,%1,%2,%3}, {%4,%5,%6,%7}, {%8,%9}, {%0,%1,%2,%3};\n"
        : "+f"(d[0]), "+f"(d[1]), "+f"(d[2]), "+f"(d[3])
        : "r"(a[0]), "r"(a[1]), "r"(a[2]), "r"(a[3]),
          "r"(b[0]), "r"(b[1]));
}

__device__ __forceinline__ uint32_t pack_h2(float x, float y) {
    __half2 h = __floats2half2_rn(x, y);
    return *(uint32_t*)&h;
}

__device__ __forceinline__ uint32_t cvta_smem(const void* p) {
    uint32_t a;
    asm("{ .reg .u64 t; cvta.to.shared.u64 t, %1; cvt.u32.u64 %0, t; }"
        : "=r"(a) : "l"(p));
    return a;
}

__device__ __forceinline__ void ldsm_x4(uint32_t* r, uint32_t a) {
    asm volatile("ldmatrix.sync.aligned.m8n8.x4.shared.b16 {%0,%1,%2,%3}, [%4];"
                 : "=r"(r[0]), "=r"(r[1]), "=r"(r[2]), "=r"(r[3]) : "r"(a));
}
__device__ __forceinline__ void ldsm_x4_t(uint32_t* r, uint32_t a) {
    asm volatile("ldmatrix.sync.aligned.m8n8.x4.trans.shared.b16 {%0,%1,%2,%3}, [%4];"
                 : "=r"(r[0]), "=r"(r[1]), "=r"(r[2]), "=r"(r[3]) : "r"(a));
}

__device__ __forceinline__ void cp16(uint32_t dst, const void* src, int nbytes) {
    asm volatile("cp.async.cg.shared.global [%0], [%1], 16, %2;"
                 :: "r"(dst), "l"(src), "r"(nbytes));
}
#define CP_COMMIT asm volatile("cp.async.commit_group;")
#define CP_WAIT0  asm volatile("cp.async.wait_group 0;")
#define CP_WAIT1  asm volatile("cp.async.wait_group 1;")

// XOR-swizzled row layouts
__device__ __forceinline__ int swz32(int row, int cp) {       // 32-u32 rows
    return row * 32 + ((((cp >> 2) ^ (row & 7)) << 2) | (cp & 3));
}
__device__ __forceinline__ int swz64(int row, int cp) {       // 64-u32 rows
    return row * 64 + ((((cp >> 2) ^ (row & 7)) << 2) | (cp & 3));
}

// ---------------------------------------------------------------------------
__global__ void f2h_kernel(const float* __restrict__ in, __half* __restrict__ out,
                           int n) {
    int i = (blockIdx.x * blockDim.x + threadIdx.x) * 4;
    if (i >= n) return;
    float4 v = *(const float4*)(in + i);
    uint2 o;
    o.x = pack_h2(v.x, v.y);
    o.y = pack_h2(v.z, v.w);
    *(uint2*)(out + i) = o;
}

__global__ void pegen_kernel(__half* __restrict__ peh) {
    int idx = blockIdx.x * blockDim.x + threadIdx.x;
    if (idx >= LPE * DMODEL) return;
    int l  = idx >> 10;
    int kk = idx & 1023;
    int p2 = kk & ~1;
    float expnt = (float)p2 / 1024.0f;
    float denom = powf(10000.0f, expnt);
    float t = (float)(l - 1022);
    float ang = t / denom;
    float v = (kk & 1) ? cosf(ang) : sinf(ang);
    peh[idx] = __float2half_rn(v * 0.03125f);
}

// pbias[h][l]; warp per (h,l)
__global__ void pbias_kernel(const __half* __restrict__ pek,
                             const float* __restrict__ cb,
                             const float* __restrict__ pb,
                             float* __restrict__ pbias) {
    int gw = (blockIdx.x * blockDim.x + threadIdx.x) >> 5;
    int lane = threadIdx.x & 31;
    if (gw >= NHEAD * 2048) return;
    int h = gw >> 11, l = gw & 2047;
    float s = 0.0f;
    if (l < LPE) {
        const __half* row = pek + (size_t)l * DMODEL + h * DHEAD;
        float d0 = pb[h * DHEAD + lane]      - cb[h * DHEAD + lane];
        float d1 = pb[h * DHEAD + 32 + lane] - cb[h * DHEAD + 32 + lane];
        s = d0 * __half2float(row[lane]) + d1 * __half2float(row[32 + lane]);
#pragma unroll
        for (int off = 16; off; off >>= 1)
            s += __shfl_xor_sync(0xffffffffu, s, off);
    }
    if (lane == 0) pbias[gw] = s;
}

// ===========================================================================
// All-half GEMM (exact R13 config): double-buffered cp.async + ldmatrix.
// C[M,N] = A[M,K] @ B[K,N].  BM=128, BN=128, BK=64, 256 threads, 64 KB smem.
// ===========================================================================
#define F_STAGE 4096
#define GEMMH_SMEM_BYTES (4 * F_STAGE * 4)   // 64 KB

template <bool C_HALF>
__global__ __launch_bounds__(256)
void gemm_h_kernel(const __half* __restrict__ A, const __half* __restrict__ B,
                   void* __restrict__ Cv, int M, int N, int K) {
    extern __shared__ uint32_t smu[];
    uint32_t smemb = cvta_smem(smu);

    float*  Cf = (float*)Cv;
    __half* Ch = (__half*)Cv;

    int tid  = threadIdx.x;
    int wid  = tid >> 5;
    int lane = tid & 31;
    int g    = lane >> 2;
    int tg   = lane & 3;
    int wm0  = (wid >> 2) * 64;
    int wn0  = (wid & 3) * 32;
    int bm = blockIdx.y * 128;
    int bn = blockIdx.x * 128;

    int rA = (lane & 7) + 8 * ((lane >> 3) & 1);
    int cA = 4 * (lane >> 4);
    int rV = lane & 15;
    int cV = 4 * (lane >> 4);

    float acc[4][4][4];
#pragma unroll
    for (int mt = 0; mt < 4; mt++)
#pragma unroll
        for (int nt = 0; nt < 4; nt++)
#pragma unroll
            for (int r = 0; r < 4; r++) acc[mt][nt][r] = 0.0f;

    auto stage = [&](int s, int k0) {
        uint32_t asB = smemb + (s * F_STAGE) * 4;
        uint32_t bsB = smemb + ((2 + s) * F_STAGE) * 4;
#pragma unroll
        for (int it = 0; it < 4; it++) {
            int idx = tid + 256 * it;
            int i = idx >> 3, gq = idx & 7;
            int gr = bm + i;
            uint32_t dst = asB + 4 * (i * 32 + ((gq ^ (i & 7)) << 2));
            cp16(dst, A + (size_t)gr * K + k0 + 8 * gq, gr < M ? 16 : 0);
        }
#pragma unroll
        for (int it = 0; it < 4; it++) {
            int idx = tid + 256 * it;
            int kr = idx >> 4, cq = idx & 15;
            uint32_t dst = bsB + 4 * (kr * 64 + ((cq ^ (kr & 7)) << 2));
            cp16(dst, B + (size_t)(k0 + kr) * N + bn + 8 * cq, 16);
        }
    };

    auto compute = [&](int s) {
        uint32_t asB = smemb + (s * F_STAGE) * 4;
        uint32_t bsB = smemb + ((2 + s) * F_STAGE) * 4;
#pragma unroll
        for (int kc = 0; kc < 4; kc++) {
            uint32_t af[4][4], bf[2][4];
#pragma unroll
            for (int mt = 0; mt < 4; mt++)
                ldsm_x4(af[mt], asB + 4 * swz32(wm0 + 16 * mt + rA, 8 * kc + cA));
#pragma unroll
            for (int np = 0; np < 2; np++)
                ldsm_x4_t(bf[np], bsB + 4 * swz64(16 * kc + rV,
                                                  wn0 / 2 + 8 * np + cV));
#pragma unroll
            for (int mt = 0; mt < 4; mt++)
#pragma unroll
                for (int np = 0; np < 2; np++) {
                    mma_f16(acc[mt][2 * np],     af[mt], bf[np]);
                    mma_f16(acc[mt][2 * np + 1], af[mt], bf[np] + 2);
                }
        }
    };

    int T = K >> 6;
    stage(0, 0);
    CP_COMMIT;

    for (int t = 0; t < T; t++) {
        CP_WAIT0;
        __syncthreads();
        if (t + 1 < T) {
            stage((t + 1) & 1, (t + 1) << 6);
            CP_COMMIT;
        }
        compute(t & 1);
    }

#pragma unroll
    for (int mt = 0; mt < 4; mt++) {
        int r0 = bm + wm0 + mt * 16 + g;
        int r1 = r0 + 8;
#pragma unroll
        for (int nt = 0; nt < 4; nt++) {
            int col = bn + wn0 + nt * 8 + 2 * tg;
            if (C_HALF) {
                if (r0 < M)
                    *(uint32_t*)(Ch + (size_t)r0 * N + col) =
                        pack_h2(acc[mt][nt][0], acc[mt][nt][1]);
                if (r1 < M)
                    *(uint32_t*)(Ch + (size_t)r1 * N + col) =
                        pack_h2(acc[mt][nt][2], acc[mt][nt][3]);
            } else {
                if (r0 < M)
                    *(float2*)(Cf + (size_t)r0 * N + col) =
                        make_float2(acc[mt][nt][0], acc[mt][nt][1]);
                if (r1 < M)
                    *(float2*)(Cf + (size_t)r1 * N + col) =
                        make_float2(acc[mt][nt][2], acc[mt][nt][3]);
            }
        }
    }
}

// ===========================================================================
// Attention v9: v8 + band fragments via ldmatrix.x4 (2 tiles per instr:
// lane>>4 selects tile, (lane>>3)&1 selects k-half; per-8-row bases keep
// ring wrap safe).  512 threads, 1 CTA/SM.
// ===========================================================================
#define A8_KS 0
#define A8_VS 4096
#define A8_PE 8192
#define A8_BIAS 20480
#define A8_MSK 20864
#define A8_U 20928
#define A8_SMEM_BYTES (42432 * 4)
#define SPAD 84
#define SLAB5 1344

__global__ __launch_bounds__(512, 1)
void attn_mma9_kernel(const __half* __restrict__ qkvh,
                      const __half* __restrict__ pekh,
                      const unsigned char* __restrict__ mask,
                      const float* __restrict__ cb,
                      const float* __restrict__ pbias,
                      __half* __restrict__ aoh) {
    extern __shared__ float sm[];
    uint32_t* PElu = (uint32_t*)sm + A8_PE;
    float* Bias = sm + A8_BIAS;
    float* Msk  = sm + A8_MSK;
    float* U    = sm + A8_U;
    uint32_t* Qs = (uint32_t*)U;
    uint32_t smemb = cvta_smem(sm);

    int tid = threadIdx.x;
    int w = tid >> 5;
    int lane = tid & 31;
    int g = lane >> 2;
    int tg = lane & 3;
    int qt = blockIdx.x & 3;
    int bh = blockIdx.x >> 2;
    int h  = bh & 15;
    int b  = bh >> 4;
    int q0 = qt * 256;

    uint32_t ksB = smemb + A8_KS * 4;
    uint32_t vsB = smemb + A8_VS * 4;
    uint32_t peB = smemb + A8_PE * 4;
    uint32_t pB  = smemb + (A8_U + w * SLAB5) * 4;

    int rA = (lane & 7) + 8 * ((lane >> 3) & 1);
    int cA = 4 * (lane >> 4);
    int rB = 8 * (lane >> 4) + (lane & 7);
    int cB = 4 * ((lane >> 3) & 1);
    int rV = lane & 15;
    int cV = 4 * (lane >> 4);
    int tI = lane >> 4;               // band tile selector within x4

    const float* cbh = cb + h * DHEAD;
    const float* pbh_bias = pbias + h * 2048;
    int lbase0 = 767 - q0;

    auto stage_kv = [&](int s, int k0s) {
        int i = tid >> 3, gq = tid & 7;
        size_t base = ((size_t)(b * SEQ + k0s + i)) * 3072 + h * 192;
        uint32_t off = 4 * (i * 32 + ((gq ^ (i & 7)) << 2));
        cp16(ksB + s * 8192 + off, qkvh + base + 64 + 8 * gq, 16);
        cp16(vsB + s * 8192 + off, qkvh + base + 128 + 8 * gq, 16);
    };

    stage_kv(0, 0);
    CP_COMMIT;

    // ---- Prologue: Qc, PE [0,320), Bias ----
    for (int idx = tid; idx < 2048; idx += 512) {
        int i = idx >> 3, gq = idx & 7;
        int c8 = gq * 8;
        uint4 v = *(const uint4*)(qkvh + ((size_t)(b * SEQ + q0 + i)) * 3072
                                  + h * 192 + c8);
        __half2* hp = (__half2*)&v;
        uint4 o;
#pragma unroll
        for (int e = 0; e < 4; e++) {
            float2 f = __half22float2(hp[e]);
            ((uint32_t*)&o)[e] = pack_h2(f.x + cbh[c8 + 2 * e],
                                         f.y + cbh[c8 + 2 * e + 1]);
        }
        *(uint4*)(Qs + i * 32 + ((gq ^ (i & 7)) << 2)) = o;
    }
    for (int idx = tid; idx < 2560; idx += 512) {
        int sl_ = idx >> 3, gq = idx & 7;
        int lg = lbase0 + sl_;
        uint4 v = (lg >= 0 && lg < LPE)
            ? *(const uint4*)(pekh + (size_t)lg * DMODEL + h * DHEAD + 8 * gq)
            : make_uint4(0u, 0u, 0u, 0u);
        *(uint4*)(PElu + sl_ * 32 + ((gq ^ (sl_ & 7)) << 2)) = v;
    }
    if (tid < 320) {
        int lg = lbase0 + tid;
        Bias[tid] = (lg >= 0 && lg < LPE) ? pbh_bias[lg] : 0.0f;
    }
    __syncthreads();

    uint32_t qcf[4][4];
    int r0l = 16 * w + g, r1l = r0l + 8;
#pragma unroll
    for (int kc = 0; kc < 4; kc++) {
        qcf[kc][0] = Qs[swz32(r0l, 8 * kc + tg)];
        qcf[kc][1] = Qs[swz32(r1l, 8 * kc + tg)];
        qcf[kc][2] = Qs[swz32(r0l, 8 * kc + tg + 4)];
        qcf[kc][3] = Qs[swz32(r1l, 8 * kc + tg + 4)];
    }

    bool zq0 = (q0 == 0 && w == 0 && g == 0);

    float oac[8][4];
#pragma unroll
    for (int nt = 0; nt < 8; nt++)
#pragma unroll
        for (int r = 0; r < 4; r++) oac[nt][r] = 0.0f;
    float m0 = -1e30f, m1 = -1e30f, l0 = 0.0f, l1 = 0.0f;

    float* slab = U + w * SLAB5;
    uint32_t* P32 = (uint32_t*)slab;
    int s0base = 30 - 2 * w;

    for (int kt = 0; kt < 16; kt++) {
        int k0 = kt * 64;
        int ktm = (64 * kt) % 384;
        int s = kt & 1;
        __syncthreads();

        if (kt < 15) {
            stage_kv(s ^ 1, k0 + 64);
            CP_COMMIT;
            {
                int r = tid >> 3, gq = tid & 7;
                int off = 64 * kt + 320 + r;
                int slot = off % 384;
                int lg = lbase0 + off;
                uint4 v = (lg >= 0 && lg < LPE)
                    ? *(const uint4*)(pekh + (size_t)lg * DMODEL + h * DHEAD + 8 * gq)
                    : make_uint4(0u, 0u, 0u, 0u);
                *(uint4*)(PElu + slot * 32 + ((gq ^ (slot & 7)) << 2)) = v;
            }
            if (tid < 64) {
                int off = 64 * kt + 320 + tid;
                int lg = lbase0 + off;
                Bias[off % 384] = (lg >= 0 && lg < LPE) ? pbh_bias[lg] : 0.0f;
            }
        }
        if (tid < 64) Msk[tid] = mask[b * SEQ + k0 + tid] ? -1e30f : 0.0f;

        if (kt < 15) { CP_WAIT1; } else { CP_WAIT0; }
        __syncthreads();

        uint32_t ksS = ksB + s * 8192;
        uint32_t vsS = vsB + s * 8192;

        // ---- Band: Spos = Qc @ PE^T + bias (5 tile-pairs via x4) ----
#pragma unroll
        for (int p = 0; p < 5; p++) {
            int mpair = s0base + 2 * p;
            int m_t = mpair + tI;
            int sr_t = ktm + 8 * m_t; if (sr_t >= 384) sr_t -= 384;
            int rowP = sr_t + (lane & 7);
            float sp0[4] = {0.f, 0.f, 0.f, 0.f};
            float sp1[4] = {0.f, 0.f, 0.f, 0.f};
#pragma unroll
            for (int kc = 0; kc < 4; kc++) {
                uint32_t bf[4];
                ldsm_x4(bf, peB + 4 * swz32(rowP, 8 * kc + cB));
                mma_f16(sp0, qcf[kc], bf);
                mma_f16(sp1, qcf[kc], bf + 2);
            }
#pragma unroll
            for (int e = 0; e < 2; e++) {
                const float* sp = (e == 0) ? sp0 : sp1;
                int m = mpair + e;
                int bidx = ktm + 8 * m + 2 * tg; if (bidx >= 384) bidx -= 384;
                float b0 = Bias[bidx], b1 = Bias[bidx + 1];
                int cc0 = 8 * (2 * p + e) + 2 * tg;
                slab[g * SPAD + cc0]           = sp[0] + b0;
                slab[g * SPAD + cc0 + 1]       = sp[1] + b1;
                slab[(g + 8) * SPAD + cc0]     = sp[2] + b0;
                slab[(g + 8) * SPAD + cc0 + 1] = sp[3] + b1;
            }
        }
        __syncwarp();

        // ---- Content scores: Qc @ K^T ----
        float sc[8][4];
#pragma unroll
        for (int nt = 0; nt < 8; nt++)
#pragma unroll
            for (int r = 0; r < 4; r++) sc[nt][r] = 0.0f;
#pragma unroll
        for (int ntp = 0; ntp < 4; ntp++) {
            int rowK = 16 * ntp + rB;
#pragma unroll
            for (int kc = 0; kc < 4; kc++) {
                uint32_t r[4];
                ldsm_x4(r, ksS + 4 * swz32(rowK, 8 * kc + cB));
                mma_f16(sc[2 * ntp],     qcf[kc], r);
                mma_f16(sc[2 * ntp + 1], qcf[kc], r + 2);
            }
        }

        // ---- Gather band diag + combine + mask + row max ----
        float mt0 = -1e30f, mt1 = -1e30f;
#pragma unroll
        for (int nt = 0; nt < 8; nt++) {
            int j0 = nt * 8 + 2 * tg;
            int c00 = j0 - g + 15;
            int c10 = j0 - g + 7;
            float p0 = slab[g * SPAD + c00];
            float p1 = slab[g * SPAD + c00 + 1];
            float p2 = slab[(g + 8) * SPAD + c10];
            float p3 = slab[(g + 8) * SPAD + c10 + 1];
            if (kt == 0 && nt == 0 && tg == 0) { p0 = 0.0f; p2 = 0.0f; }
            if (zq0) { p0 = 0.0f; p1 = 0.0f; }
            float mk0 = Msk[j0], mk1 = Msk[j0 + 1];
            sc[nt][0] = (sc[nt][0] + p0) * 0.125f + mk0;
            sc[nt][1] = (sc[nt][1] + p1) * 0.125f + mk1;
            sc[nt][2] = (sc[nt][2] + p2) * 0.125f + mk0;
            sc[nt][3] = (sc[nt][3] + p3) * 0.125f + mk1;
            mt0 = fmaxf(mt0, fmaxf(sc[nt][0], sc[nt][1]));
            mt1 = fmaxf(mt1, fmaxf(sc[nt][2], sc[nt][3]));
        }
        mt0 = fmaxf(mt0, __shfl_xor_sync(0xffffffffu, mt0, 1));
        mt0 = fmaxf(mt0, __shfl_xor_sync(0xffffffffu, mt0, 2));
        mt1 = fmaxf(mt1, __shfl_xor_sync(0xffffffffu, mt1, 1));
        mt1 = fmaxf(mt1, __shfl_xor_sync(0xffffffffu, mt1, 2));

        // ---- Online softmax ----
        float mn0 = fmaxf(m0, mt0), mn1 = fmaxf(m1, mt1);
        float c0 = __expf(m0 - mn0), c1 = __expf(m1 - mn1);
        m0 = mn0; m1 = mn1;
#pragma unroll
        for (int nt = 0; nt < 8; nt++) {
            oac[nt][0] *= c0; oac[nt][1] *= c0;
            oac[nt][2] *= c1; oac[nt][3] *= c1;
        }
        float rs0 = 0.0f, rs1 = 0.0f;
#pragma unroll
        for (int nt = 0; nt < 8; nt++) {
            sc[nt][0] = __expf(sc[nt][0] - mn0);
            sc[nt][1] = __expf(sc[nt][1] - mn0);
            sc[nt][2] = __expf(sc[nt][2] - mn1);
            sc[nt][3] = __expf(sc[nt][3] - mn1);
            rs0 += sc[nt][0] + sc[nt][1];
            rs1 += sc[nt][2] + sc[nt][3];
        }
        rs0 += __shfl_xor_sync(0xffffffffu, rs0, 1);
        rs0 += __shfl_xor_sync(0xffffffffu, rs0, 2);
        rs1 += __shfl_xor_sync(0xffffffffu, rs1, 1);
        rs1 += __shfl_xor_sync(0xffffffffu, rs1, 2);
        l0 = l0 * c0 + rs0;
        l1 = l1 * c1 + rs1;

        __syncwarp();

        // ---- Write P (fp16 half2 pairs) ----
#pragma unroll
        for (int nt = 0; nt < 8; nt++) {
            P32[swz32(g,     4 * nt + tg)] = pack_h2(sc[nt][0], sc[nt][1]);
            P32[swz32(g + 8, 4 * nt + tg)] = pack_h2(sc[nt][2], sc[nt][3]);
        }
        __syncwarp();

        // ---- O += P @ V ----
        uint32_t pf[4][4];
#pragma unroll
        for (int kc = 0; kc < 4; kc++)
            ldsm_x4(pf[kc], pB + 4 * swz32(rA, 8 * kc + cA));
#pragma unroll
        for (int ntp = 0; ntp < 4; ntp++) {
            int cpV = 8 * ntp + cV;
#pragma unroll
            for (int kc = 0; kc < 4; kc++) {
                uint32_t r[4];
                ldsm_x4_t(r, vsS + 4 * swz32(16 * kc + rV, cpV));
                mma_f16(oac[2 * ntp],     pf[kc], r);
                mma_f16(oac[2 * ntp + 1], pf[kc], r + 2);
            }
        }
    }

    // ---- Epilogue (half out) ----
    float inv0 = 1.0f / l0, inv1 = 1.0f / l1;
    int r0 = q0 + r0l, r1 = q0 + r1l;
    size_t rowA = ((size_t)(b * SEQ + r0)) * DMODEL + h * DHEAD;
    size_t rowB = ((size_t)(b * SEQ + r1)) * DMODEL + h * DHEAD;
#pragma unroll
    for (int nt = 0; nt < 8; nt++) {
        int col = nt * 8 + 2 * tg;
        *(uint32_t*)(aoh + rowA + col) =
            pack_h2(oac[nt][0] * inv0, oac[nt][1] * inv0);
        *(uint32_t*)(aoh + rowB + col) =
            pack_h2(oac[nt][2] * inv1, oac[nt][3] * inv1);
    }
}

// ---------------------------------------------------------------------------
extern "C" void kernel_launch(void* const* d_in, const int* in_sizes, int n_in,
                              void* d_out, int out_size) {
    const float* x          = (const float*)d_in[0];
    const unsigned char* mk = (const unsigned char*)d_in[1];
    const float* Wqkv       = (const float*)d_in[2];
    const float* Wpe        = (const float*)d_in[3];
    const float* Wo         = (const float*)d_in[4];
    const float* cb         = (const float*)d_in[5];
    const float* pb         = (const float*)d_in[6];
    float* out              = (float*)d_out;

    __half *xh, *wqkvh, *wpeh, *woh, *qkvh, *peh, *pekh, *aoh;
    float *pbias;
    cudaGetSymbolAddress((void**)&xh,    g_xh);
    cudaGetSymbolAddress((void**)&wqkvh, g_wqkvh);
    cudaGetSymbolAddress((void**)&wpeh,  g_wpeh);
    cudaGetSymbolAddress((void**)&woh,   g_woh);
    cudaGetSymbolAddress((void**)&qkvh,  g_qkvh);
    cudaGetSymbolAddress((void**)&peh,   g_peh);
    cudaGetSymbolAddress((void**)&pekh,  g_pekh);
    cudaGetSymbolAddress((void**)&aoh,   g_aoh);
    cudaGetSymbolAddress((void**)&pbias, g_pbias);

    cudaFuncSetAttribute(gemm_h_kernel<true>,
                         cudaFuncAttributeMaxDynamicSharedMemorySize,
                         GEMMH_SMEM_BYTES);
    cudaFuncSetAttribute(gemm_h_kernel<false>,
                         cudaFuncAttributeMaxDynamicSharedMemorySize,
                         GEMMH_SMEM_BYTES);
    cudaFuncSetAttribute(attn_mma9_kernel,
                         cudaFuncAttributeMaxDynamicSharedMemorySize,
                         A8_SMEM_BYTES);

    f2h_kernel<<<(BSZ * SEQ * DMODEL / 4 + 255) / 256, 256>>>(x, xh,
                                                              BSZ * SEQ * DMODEL);
    f2h_kernel<<<(DMODEL * 3 * DMODEL / 4 + 255) / 256, 256>>>(Wqkv, wqkvh,
                                                               DMODEL * 3 * DMODEL);
    f2h_kernel<<<(DMODEL * DMODEL / 4 + 255) / 256, 256>>>(Wpe, wpeh,
                                                           DMODEL * DMODEL);
    f2h_kernel<<<(DMODEL * DMODEL / 4 + 255) / 256, 256>>>(Wo, woh,
                                                           DMODEL * DMODEL);
    pegen_kernel<<<(LPE * DMODEL + 255) / 256, 256>>>(peh);

    {
        dim3 grid(3072 / 128, 4096 / 128);
        gemm_h_kernel<true><<<grid, 256, GEMMH_SMEM_BYTES>>>(
            xh, wqkvh, qkvh, BSZ * SEQ, 3 * DMODEL, DMODEL);
    }
    {
        dim3 grid(1024 / 128, (LPE + 127) / 128);
        gemm_h_kernel<true><<<grid, 256, GEMMH_SMEM_BYTES>>>(
            peh, wpeh, pekh, LPE, DMODEL, DMODEL);
    }

    pbias_kernel<<<(NHEAD * 2048 * 32) / 256, 256>>>(pekh, cb, pb, pbias);

    attn_mma9_kernel<<<BSZ * NHEAD * (SEQ / 256), 512, A8_SMEM_BYTES>>>(
        qkvh, pekh, mk, cb, pbias, aoh);

    {
        dim3 grid(1024 / 128, 4096 / 128);
        gemm_h_kernel<false><<<grid, 256, GEMMH_SMEM_BYTES>>>(
            aoh, woh, out, BSZ * SEQ, DMODEL, DMODEL);
    }
}

// round 17
// speedup vs baseline: 1.0466x; 1.0196x over previous
#include <cuda_runtime.h>
#include <cuda_bf16.h>
#include <cuda_fp16.h>
#include <cstdint>
#include <math.h>

// Problem constants
#define BSZ 4
#define SEQ 1024
#define DMODEL 1024
#define NHEAD 16
#define DHEAD 64
#define LPE 2045   // 2*s-1, s = 1023

// Scratch (all operands fp16)
__device__ __half g_xh  [BSZ * SEQ * DMODEL];
__device__ __half g_wqkvh[DMODEL * 3 * DMODEL];
__device__ __half g_wpeh [DMODEL * DMODEL];
__device__ __half g_woh  [DMODEL * DMODEL];
__device__ __half g_qkvh[BSZ * SEQ * 3 * DMODEL];
__device__ __half g_peh [LPE * DMODEL];
__device__ __half g_pekh[LPE * DMODEL];
__device__ __half g_aoh [BSZ * SEQ * DMODEL];

// ---------------------------------------------------------------------------
__device__ __forceinline__ void mma_f16(float* d, const uint32_t* a,
                                        const uint32_t* b) {
    asm volatile(
        "mma.sync.aligned.m16n8k16.row.col.f32.f16.f16.f32 "
        "{%0,%1,%2,%3}, {%4,%5,%6,%7}, {%8,%9}, {%0,%1,%2,%3};\n"
        : "+f"(d[0]), "+f"(d[1]), "+f"(d[2]), "+f"(d[3])
        : "r"(a[0]), "r"(a[1]), "r"(a[2]), "r"(a[3]),
          "r"(b[0]), "r"(b[1]));
}

__device__ __forceinline__ uint32_t pack_h2(float x, float y) {
    __half2 h = __floats2half2_rn(x, y);
    return *(uint32_t*)&h;
}

__device__ __forceinline__ uint32_t cvta_smem(const void* p) {
    uint32_t a;
    asm("{ .reg .u64 t; cvta.to.shared.u64 t, %1; cvt.u32.u64 %0, t; }"
        : "=r"(a) : "l"(p));
    return a;
}

__device__ __forceinline__ void ldsm_x4(uint32_t* r, uint32_t a) {
    asm volatile("ldmatrix.sync.aligned.m8n8.x4.shared.b16 {%0,%1,%2,%3}, [%4];"
                 : "=r"(r[0]), "=r"(r[1]), "=r"(r[2]), "=r"(r[3]) : "r"(a));
}
__device__ __forceinline__ void ldsm_x4_t(uint32_t* r, uint32_t a) {
    asm volatile("ldmatrix.sync.aligned.m8n8.x4.trans.shared.b16 {%0,%1,%2,%3}, [%4];"
                 : "=r"(r[0]), "=r"(r[1]), "=r"(r[2]), "=r"(r[3]) : "r"(a));
}

__device__ __forceinline__ void cp16(uint32_t dst, const void* src, int nbytes) {
    asm volatile("cp.async.cg.shared.global [%0], [%1], 16, %2;"
                 :: "r"(dst), "l"(src), "r"(nbytes));
}
#define CP_COMMIT asm volatile("cp.async.commit_group;")
#define CP_WAIT0  asm volatile("cp.async.wait_group 0;")
#define CP_WAIT1  asm volatile("cp.async.wait_group 1;")

// XOR-swizzled row layouts
__device__ __forceinline__ int swz32(int row, int cp) {       // 32-u32 rows
    return row * 32 + ((((cp >> 2) ^ (row & 7)) << 2) | (cp & 3));
}
__device__ __forceinline__ int swz64(int row, int cp) {       // 64-u32 rows
    return row * 64 + ((((cp >> 2) ^ (row & 7)) << 2) | (cp & 3));
}

// ===========================================================================
// Fused prep: 4 x f2h conversions + sinusoidal PE generation, one launch.
// Segments (4-elem units): x 1048576 | wqkv 786432 | wpe 262144 | wo 262144;
// then pegen 2094080 single elements.  Total threads 4453376 = 17396 * 256.
// ===========================================================================
#define PREP_N0 1048576
#define PREP_N1 (PREP_N0 + 786432)
#define PREP_N2 (PREP_N1 + 262144)
#define PREP_N3 (PREP_N2 + 262144)
#define PREP_TOTAL (PREP_N3 + LPE * DMODEL)

__global__ void prep_kernel(const float* __restrict__ x,
                            const float* __restrict__ wqkv,
                            const float* __restrict__ wpe,
                            const float* __restrict__ wo,
                            __half* __restrict__ xh,
                            __half* __restrict__ wqkvh,
                            __half* __restrict__ wpeh,
                            __half* __restrict__ woh,
                            __half* __restrict__ peh) {
    int gid = blockIdx.x * blockDim.x + threadIdx.x;
    if (gid < PREP_N3) {
        const float* in;
        __half* out;
        int base;
        if (gid < PREP_N0)      { in = x;    out = xh;    base = gid; }
        else if (gid < PREP_N1) { in = wqkv; out = wqkvh; base = gid - PREP_N0; }
        else if (gid < PREP_N2) { in = wpe;  out = wpeh;  base = gid - PREP_N1; }
        else                    { in = wo;   out = woh;   base = gid - PREP_N2; }
        int i = base * 4;
        float4 v = *(const float4*)(in + i);
        uint2 o;
        o.x = pack_h2(v.x, v.y);
        o.y = pack_h2(v.z, v.w);
        *(uint2*)(out + i) = o;
    } else {
        int idx = gid - PREP_N3;
        if (idx < LPE * DMODEL) {
            int l  = idx >> 10;
            int kk = idx & 1023;
            int p2 = kk & ~1;
            float expnt = (float)p2 / 1024.0f;
            float denom = powf(10000.0f, expnt);
            float t = (float)(l - 1022);
            float ang = t / denom;
            float v = (kk & 1) ? cosf(ang) : sinf(ang);
            peh[idx] = __float2half_rn(v * 0.03125f);
        }
    }
}

// ===========================================================================
// All-half GEMM (exact R13 config): double-buffered cp.async + ldmatrix.
// ===========================================================================
#define F_STAGE 4096
#define GEMMH_SMEM_BYTES (4 * F_STAGE * 4)   // 64 KB

template <bool C_HALF>
__global__ __launch_bounds__(256)
void gemm_h_kernel(const __half* __restrict__ A, const __half* __restrict__ B,
                   void* __restrict__ Cv, int M, int N, int K) {
    extern __shared__ uint32_t smu[];
    uint32_t smemb = cvta_smem(smu);

    float*  Cf = (float*)Cv;
    __half* Ch = (__half*)Cv;

    int tid  = threadIdx.x;
    int wid  = tid >> 5;
    int lane = tid & 31;
    int g    = lane >> 2;
    int tg   = lane & 3;
    int wm0  = (wid >> 2) * 64;
    int wn0  = (wid & 3) * 32;
    int bm = blockIdx.y * 128;
    int bn = blockIdx.x * 128;

    int rA = (lane & 7) + 8 * ((lane >> 3) & 1);
    int cA = 4 * (lane >> 4);
    int rV = lane & 15;
    int cV = 4 * (lane >> 4);

    float acc[4][4][4];
#pragma unroll
    for (int mt = 0; mt < 4; mt++)
#pragma unroll
        for (int nt = 0; nt < 4; nt++)
#pragma unroll
            for (int r = 0; r < 4; r++) acc[mt][nt][r] = 0.0f;

    auto stage = [&](int s, int k0) {
        uint32_t asB = smemb + (s * F_STAGE) * 4;
        uint32_t bsB = smemb + ((2 + s) * F_STAGE) * 4;
#pragma unroll
        for (int it = 0; it < 4; it++) {
            int idx = tid + 256 * it;
            int i = idx >> 3, gq = idx & 7;
            int gr = bm + i;
            uint32_t dst = asB + 4 * (i * 32 + ((gq ^ (i & 7)) << 2));
            cp16(dst, A + (size_t)gr * K + k0 + 8 * gq, gr < M ? 16 : 0);
        }
#pragma unroll
        for (int it = 0; it < 4; it++) {
            int idx = tid + 256 * it;
            int kr = idx >> 4, cq = idx & 15;
            uint32_t dst = bsB + 4 * (kr * 64 + ((cq ^ (kr & 7)) << 2));
            cp16(dst, B + (size_t)(k0 + kr) * N + bn + 8 * cq, 16);
        }
    };

    auto compute = [&](int s) {
        uint32_t asB = smemb + (s * F_STAGE) * 4;
        uint32_t bsB = smemb + ((2 + s) * F_STAGE) * 4;
#pragma unroll
        for (int kc = 0; kc < 4; kc++) {
            uint32_t af[4][4], bf[2][4];
#pragma unroll
            for (int mt = 0; mt < 4; mt++)
                ldsm_x4(af[mt], asB + 4 * swz32(wm0 + 16 * mt + rA, 8 * kc + cA));
#pragma unroll
            for (int np = 0; np < 2; np++)
                ldsm_x4_t(bf[np], bsB + 4 * swz64(16 * kc + rV,
                                                  wn0 / 2 + 8 * np + cV));
#pragma unroll
            for (int mt = 0; mt < 4; mt++)
#pragma unroll
                for (int np = 0; np < 2; np++) {
                    mma_f16(acc[mt][2 * np],     af[mt], bf[np]);
                    mma_f16(acc[mt][2 * np + 1], af[mt], bf[np] + 2);
                }
        }
    };

    int T = K >> 6;
    stage(0, 0);
    CP_COMMIT;

    for (int t = 0; t < T; t++) {
        CP_WAIT0;
        __syncthreads();
        if (t + 1 < T) {
            stage((t + 1) & 1, (t + 1) << 6);
            CP_COMMIT;
        }
        compute(t & 1);
    }

#pragma unroll
    for (int mt = 0; mt < 4; mt++) {
        int r0 = bm + wm0 + mt * 16 + g;
        int r1 = r0 + 8;
#pragma unroll
        for (int nt = 0; nt < 4; nt++) {
            int col = bn + wn0 + nt * 8 + 2 * tg;
            if (C_HALF) {
                if (r0 < M)
                    *(uint32_t*)(Ch + (size_t)r0 * N + col) =
                        pack_h2(acc[mt][nt][0], acc[mt][nt][1]);
                if (r1 < M)
                    *(uint32_t*)(Ch + (size_t)r1 * N + col) =
                        pack_h2(acc[mt][nt][2], acc[mt][nt][3]);
            } else {
                if (r0 < M)
                    *(float2*)(Cf + (size_t)r0 * N + col) =
                        make_float2(acc[mt][nt][0], acc[mt][nt][1]);
                if (r1 < M)
                    *(float2*)(Cf + (size_t)r1 * N + col) =
                        make_float2(acc[mt][nt][2], acc[mt][nt][3]);
            }
        }
    }
}

// ===========================================================================
// Attention v10: v9 + inline pos-bias (computed while staging PE rows:
// partial dot vs Dsm[64] delta table + width-8 shuffle reduce).
// 512 threads, 1 CTA/SM.
// Smem (u32): Ks[2] 4096 | Vs[2] 4096 | PE 12288 | Bias 384 | Msk 64 |
//             Dsm 64 | U 21504  -> 42496 u32 = 169984 B.
// ===========================================================================
#define A9_KS 0
#define A9_VS 4096
#define A9_PE 8192
#define A9_BIAS 20480
#define A9_MSK 20864
#define A9_DSM 20928
#define A9_U 20992
#define A9_SMEM_BYTES (42496 * 4)
#define SPAD 84
#define SLAB5 1344

__global__ __launch_bounds__(512, 1)
void attn_mma10_kernel(const __half* __restrict__ qkvh,
                       const __half* __restrict__ pekh,
                       const unsigned char* __restrict__ mask,
                       const float* __restrict__ cb,
                       const float* __restrict__ pb,
                       __half* __restrict__ aoh) {
    extern __shared__ float sm[];
    uint32_t* PElu = (uint32_t*)sm + A9_PE;
    float* Bias = sm + A9_BIAS;
    float* Msk  = sm + A9_MSK;
    float* Dsm  = sm + A9_DSM;
    float* U    = sm + A9_U;
    uint32_t* Qs = (uint32_t*)U;
    uint32_t smemb = cvta_smem(sm);

    int tid = threadIdx.x;
    int w = tid >> 5;
    int lane = tid & 31;
    int g = lane >> 2;
    int tg = lane & 3;
    int qt = blockIdx.x & 3;
    int bh = blockIdx.x >> 2;
    int h  = bh & 15;
    int b  = bh >> 4;
    int q0 = qt * 256;

    uint32_t ksB = smemb + A9_KS * 4;
    uint32_t vsB = smemb + A9_VS * 4;
    uint32_t peB = smemb + A9_PE * 4;
    uint32_t pB  = smemb + (A9_U + w * SLAB5) * 4;

    int rA = (lane & 7) + 8 * ((lane >> 3) & 1);
    int cA = 4 * (lane >> 4);
    int rB = 8 * (lane >> 4) + (lane & 7);
    int cB = 4 * ((lane >> 3) & 1);
    int rV = lane & 15;
    int cV = 4 * (lane >> 4);
    int tI = lane >> 4;               // band tile selector within x4

    const float* cbh = cb + h * DHEAD;
    int lbase0 = 767 - q0;

    auto stage_kv = [&](int s, int k0s) {
        int i = tid >> 3, gq = tid & 7;
        size_t base = ((size_t)(b * SEQ + k0s + i)) * 3072 + h * 192;
        uint32_t off = 4 * (i * 32 + ((gq ^ (i & 7)) << 2));
        cp16(ksB + s * 8192 + off, qkvh + base + 64 + 8 * gq, 16);
        cp16(vsB + s * 8192 + off, qkvh + base + 128 + 8 * gq, 16);
    };

    stage_kv(0, 0);
    CP_COMMIT;

    // ---- Delta table for inline pos-bias ----
    if (tid < 64) Dsm[tid] = pb[h * DHEAD + tid] - cb[h * DHEAD + tid];
    __syncthreads();

    // Partial-dot helper for a staged PE row fragment (8 halves at cols 8gq..)
    auto pe_bias_partial = [&](uint4 v, int gq) -> float {
        const __half2* hp = (const __half2*)&v;
        float p = 0.0f;
#pragma unroll
        for (int e = 0; e < 4; e++) {
            float2 f = __half22float2(hp[e]);
            p += Dsm[8 * gq + 2 * e] * f.x + Dsm[8 * gq + 2 * e + 1] * f.y;
        }
        p += __shfl_xor_sync(0xffffffffu, p, 1, 8);
        p += __shfl_xor_sync(0xffffffffu, p, 2, 8);
        p += __shfl_xor_sync(0xffffffffu, p, 4, 8);
        return p;
    };

    // ---- Prologue: Qc, PE [0,320) + Bias ----
    for (int idx = tid; idx < 2048; idx += 512) {
        int i = idx >> 3, gq = idx & 7;
        int c8 = gq * 8;
        uint4 v = *(const uint4*)(qkvh + ((size_t)(b * SEQ + q0 + i)) * 3072
                                  + h * 192 + c8);
        __half2* hp = (__half2*)&v;
        uint4 o;
#pragma unroll
        for (int e = 0; e < 4; e++) {
            float2 f = __half22float2(hp[e]);
            ((uint32_t*)&o)[e] = pack_h2(f.x + cbh[c8 + 2 * e],
                                         f.y + cbh[c8 + 2 * e + 1]);
        }
        *(uint4*)(Qs + i * 32 + ((gq ^ (i & 7)) << 2)) = o;
    }
    for (int idx = tid; idx < 2560; idx += 512) {
        int sl_ = idx >> 3, gq = idx & 7;
        int lg = lbase0 + sl_;
        uint4 v = (lg >= 0 && lg < LPE)
            ? *(const uint4*)(pekh + (size_t)lg * DMODEL + h * DHEAD + 8 * gq)
            : make_uint4(0u, 0u, 0u, 0u);
        *(uint4*)(PElu + sl_ * 32 + ((gq ^ (sl_ & 7)) << 2)) = v;
        float p = pe_bias_partial(v, gq);
        if ((tid & 7) == 0) Bias[sl_] = p;
    }
    __syncthreads();

    uint32_t qcf[4][4];
    int r0l = 16 * w + g, r1l = r0l + 8;
#pragma unroll
    for (int kc = 0; kc < 4; kc++) {
        qcf[kc][0] = Qs[swz32(r0l, 8 * kc + tg)];
        qcf[kc][1] = Qs[swz32(r1l, 8 * kc + tg)];
        qcf[kc][2] = Qs[swz32(r0l, 8 * kc + tg + 4)];
        qcf[kc][3] = Qs[swz32(r1l, 8 * kc + tg + 4)];
    }

    bool zq0 = (q0 == 0 && w == 0 && g == 0);

    float oac[8][4];
#pragma unroll
    for (int nt = 0; nt < 8; nt++)
#pragma unroll
        for (int r = 0; r < 4; r++) oac[nt][r] = 0.0f;
    float m0 = -1e30f, m1 = -1e30f, l0 = 0.0f, l1 = 0.0f;

    float* slab = U + w * SLAB5;
    uint32_t* P32 = (uint32_t*)slab;
    int s0base = 30 - 2 * w;

    for (int kt = 0; kt < 16; kt++) {
        int k0 = kt * 64;
        int ktm = (64 * kt) % 384;
        int s = kt & 1;
        __syncthreads();

        if (kt < 15) {
            stage_kv(s ^ 1, k0 + 64);
            CP_COMMIT;
            {
                int r = tid >> 3, gq = tid & 7;
                int off = 64 * kt + 320 + r;
                int slot = off % 384;
                int lg = lbase0 + off;
                uint4 v = (lg >= 0 && lg < LPE)
                    ? *(const uint4*)(pekh + (size_t)lg * DMODEL + h * DHEAD + 8 * gq)
                    : make_uint4(0u, 0u, 0u, 0u);
                *(uint4*)(PElu + slot * 32 + ((gq ^ (slot & 7)) << 2)) = v;
                float p = pe_bias_partial(v, gq);
                if ((tid & 7) == 0) Bias[slot] = p;
            }
        }
        if (tid < 64) Msk[tid] = mask[b * SEQ + k0 + tid] ? -1e30f : 0.0f;

        if (kt < 15) { CP_WAIT1; } else { CP_WAIT0; }
        __syncthreads();

        uint32_t ksS = ksB + s * 8192;
        uint32_t vsS = vsB + s * 8192;

        // ---- Band: Spos = Qc @ PE^T + bias (5 tile-pairs via x4) ----
#pragma unroll
        for (int p = 0; p < 5; p++) {
            int mpair = s0base + 2 * p;
            int m_t = mpair + tI;
            int sr_t = ktm + 8 * m_t; if (sr_t >= 384) sr_t -= 384;
            int rowP = sr_t + (lane & 7);
            float sp0[4] = {0.f, 0.f, 0.f, 0.f};
            float sp1[4] = {0.f, 0.f, 0.f, 0.f};
#pragma unroll
            for (int kc = 0; kc < 4; kc++) {
                uint32_t bf[4];
                ldsm_x4(bf, peB + 4 * swz32(rowP, 8 * kc + cB));
                mma_f16(sp0, qcf[kc], bf);
                mma_f16(sp1, qcf[kc], bf + 2);
            }
#pragma unroll
            for (int e = 0; e < 2; e++) {
                const float* sp = (e == 0) ? sp0 : sp1;
                int m = mpair + e;
                int bidx = ktm + 8 * m + 2 * tg; if (bidx >= 384) bidx -= 384;
                float b0 = Bias[bidx], b1 = Bias[bidx + 1];
                int cc0 = 8 * (2 * p + e) + 2 * tg;
                slab[g * SPAD + cc0]           = sp[0] + b0;
                slab[g * SPAD + cc0 + 1]       = sp[1] + b1;
                slab[(g + 8) * SPAD + cc0]     = sp[2] + b0;
                slab[(g + 8) * SPAD + cc0 + 1] = sp[3] + b1;
            }
        }
        __syncwarp();

        // ---- Content scores: Qc @ K^T ----
        float sc[8][4];
#pragma unroll
        for (int nt = 0; nt < 8; nt++)
#pragma unroll
            for (int r = 0; r < 4; r++) sc[nt][r] = 0.0f;
#pragma unroll
        for (int ntp = 0; ntp < 4; ntp++) {
            int rowK = 16 * ntp + rB;
#pragma unroll
            for (int kc = 0; kc < 4; kc++) {
                uint32_t r[4];
                ldsm_x4(r, ksS + 4 * swz32(rowK, 8 * kc + cB));
                mma_f16(sc[2 * ntp],     qcf[kc], r);
                mma_f16(sc[2 * ntp + 1], qcf[kc], r + 2);
            }
        }

        // ---- Gather band diag + combine + mask + row max ----
        float mt0 = -1e30f, mt1 = -1e30f;
#pragma unroll
        for (int nt = 0; nt < 8; nt++) {
            int j0 = nt * 8 + 2 * tg;
            int c00 = j0 - g + 15;
            int c10 = j0 - g + 7;
            float p0 = slab[g * SPAD + c00];
            float p1 = slab[g * SPAD + c00 + 1];
            float p2 = slab[(g + 8) * SPAD + c10];
            float p3 = slab[(g + 8) * SPAD + c10 + 1];
            if (kt == 0 && nt == 0 && tg == 0) { p0 = 0.0f; p2 = 0.0f; }
            if (zq0) { p0 = 0.0f; p1 = 0.0f; }
            float mk0 = Msk[j0], mk1 = Msk[j0 + 1];
            sc[nt][0] = (sc[nt][0] + p0) * 0.125f + mk0;
            sc[nt][1] = (sc[nt][1] + p1) * 0.125f + mk1;
            sc[nt][2] = (sc[nt][2] + p2) * 0.125f + mk0;
            sc[nt][3] = (sc[nt][3] + p3) * 0.125f + mk1;
            mt0 = fmaxf(mt0, fmaxf(sc[nt][0], sc[nt][1]));
            mt1 = fmaxf(mt1, fmaxf(sc[nt][2], sc[nt][3]));
        }
        mt0 = fmaxf(mt0, __shfl_xor_sync(0xffffffffu, mt0, 1));
        mt0 = fmaxf(mt0, __shfl_xor_sync(0xffffffffu, mt0, 2));
        mt1 = fmaxf(mt1, __shfl_xor_sync(0xffffffffu, mt1, 1));
        mt1 = fmaxf(mt1, __shfl_xor_sync(0xffffffffu, mt1, 2));

        // ---- Online softmax ----
        float mn0 = fmaxf(m0, mt0), mn1 = fmaxf(m1, mt1);
        float c0 = __expf(m0 - mn0), c1 = __expf(m1 - mn1);
        m0 = mn0; m1 = mn1;
#pragma unroll
        for (int nt = 0; nt < 8; nt++) {
            oac[nt][0] *= c0; oac[nt][1] *= c0;
            oac[nt][2] *= c1; oac[nt][3] *= c1;
        }
        float rs0 = 0.0f, rs1 = 0.0f;
#pragma unroll
        for (int nt = 0; nt < 8; nt++) {
            sc[nt][0] = __expf(sc[nt][0] - mn0);
            sc[nt][1] = __expf(sc[nt][1] - mn0);
            sc[nt][2] = __expf(sc[nt][2] - mn1);
            sc[nt][3] = __expf(sc[nt][3] - mn1);
            rs0 += sc[nt][0] + sc[nt][1];
            rs1 += sc[nt][2] + sc[nt][3];
        }
        rs0 += __shfl_xor_sync(0xffffffffu, rs0, 1);
        rs0 += __shfl_xor_sync(0xffffffffu, rs0, 2);
        rs1 += __shfl_xor_sync(0xffffffffu, rs1, 1);
        rs1 += __shfl_xor_sync(0xffffffffu, rs1, 2);
        l0 = l0 * c0 + rs0;
        l1 = l1 * c1 + rs1;

        __syncwarp();

        // ---- Write P (fp16 half2 pairs) ----
#pragma unroll
        for (int nt = 0; nt < 8; nt++) {
            P32[swz32(g,     4 * nt + tg)] = pack_h2(sc[nt][0], sc[nt][1]);
            P32[swz32(g + 8, 4 * nt + tg)] = pack_h2(sc[nt][2], sc[nt][3]);
        }
        __syncwarp();

        // ---- O += P @ V ----
        uint32_t pf[4][4];
#pragma unroll
        for (int kc = 0; kc < 4; kc++)
            ldsm_x4(pf[kc], pB + 4 * swz32(rA, 8 * kc + cA));
#pragma unroll
        for (int ntp = 0; ntp < 4; ntp++) {
            int cpV = 8 * ntp + cV;
#pragma unroll
            for (int kc = 0; kc < 4; kc++) {
                uint32_t r[4];
                ldsm_x4_t(r, vsS + 4 * swz32(16 * kc + rV, cpV));
                mma_f16(oac[2 * ntp],     pf[kc], r);
                mma_f16(oac[2 * ntp + 1], pf[kc], r + 2);
            }
        }
    }

    // ---- Epilogue (half out) ----
    float inv0 = 1.0f / l0, inv1 = 1.0f / l1;
    int r0 = q0 + r0l, r1 = q0 + r1l;
    size_t rowA = ((size_t)(b * SEQ + r0)) * DMODEL + h * DHEAD;
    size_t rowB = ((size_t)(b * SEQ + r1)) * DMODEL + h * DHEAD;
#pragma unroll
    for (int nt = 0; nt < 8; nt++) {
        int col = nt * 8 + 2 * tg;
        *(uint32_t*)(aoh + rowA + col) =
            pack_h2(oac[nt][0] * inv0, oac[nt][1] * inv0);
        *(uint32_t*)(aoh + rowB + col) =
            pack_h2(oac[nt][2] * inv1, oac[nt][3] * inv1);
    }
}

// ---------------------------------------------------------------------------
extern "C" void kernel_launch(void* const* d_in, const int* in_sizes, int n_in,
                              void* d_out, int out_size) {
    const float* x          = (const float*)d_in[0];
    const unsigned char* mk = (const unsigned char*)d_in[1];
    const float* Wqkv       = (const float*)d_in[2];
    const float* Wpe        = (const float*)d_in[3];
    const float* Wo         = (const float*)d_in[4];
    const float* cb         = (const float*)d_in[5];
    const float* pb         = (const float*)d_in[6];
    float* out              = (float*)d_out;

    __half *xh, *wqkvh, *wpeh, *woh, *qkvh, *peh, *pekh, *aoh;
    cudaGetSymbolAddress((void**)&xh,    g_xh);
    cudaGetSymbolAddress((void**)&wqkvh, g_wqkvh);
    cudaGetSymbolAddress((void**)&wpeh,  g_wpeh);
    cudaGetSymbolAddress((void**)&woh,   g_woh);
    cudaGetSymbolAddress((void**)&qkvh,  g_qkvh);
    cudaGetSymbolAddress((void**)&peh,   g_peh);
    cudaGetSymbolAddress((void**)&pekh,  g_pekh);
    cudaGetSymbolAddress((void**)&aoh,   g_aoh);

    cudaFuncSetAttribute(gemm_h_kernel<true>,
                         cudaFuncAttributeMaxDynamicSharedMemorySize,
                         GEMMH_SMEM_BYTES);
    cudaFuncSetAttribute(gemm_h_kernel<false>,
                         cudaFuncAttributeMaxDynamicSharedMemorySize,
                         GEMMH_SMEM_BYTES);
    cudaFuncSetAttribute(attn_mma10_kernel,
                         cudaFuncAttributeMaxDynamicSharedMemorySize,
                         A9_SMEM_BYTES);

    // One fused prep launch: 4 f2h conversions + PE generation
    prep_kernel<<<PREP_TOTAL / 256, 256>>>(x, Wqkv, Wpe, Wo,
                                           xh, wqkvh, wpeh, woh, peh);

    // qkv = x @ W_qkv (half C)
    {
        dim3 grid(3072 / 128, 4096 / 128);
        gemm_h_kernel<true><<<grid, 256, GEMMH_SMEM_BYTES>>>(
            xh, wqkvh, qkvh, BSZ * SEQ, 3 * DMODEL, DMODEL);
    }
    // pe_key = pe @ W_pe (half C)
    {
        dim3 grid(1024 / 128, (LPE + 127) / 128);
        gemm_h_kernel<true><<<grid, 256, GEMMH_SMEM_BYTES>>>(
            peh, wpeh, pekh, LPE, DMODEL, DMODEL);
    }

    // Fused attention (pos-bias computed inline)
    attn_mma10_kernel<<<BSZ * NHEAD * (SEQ / 256), 512, A9_SMEM_BYTES>>>(
        qkvh, pekh, mk, cb, pb, aoh);

    // out = ao @ W_o (fp32 C)
    {
        dim3 grid(1024 / 128, 4096 / 128);
        gemm_h_kernel<false><<<grid, 256, GEMMH_SMEM_BYTES>>>(
            aoh, woh, out, BSZ * SEQ, DMODEL, DMODEL);
    }
}